// round 1
// baseline (speedup 1.0000x reference)
#include <cuda_runtime.h>
#include <math.h>

#define L_SEQ  2048
#define NB     4
#define EMB    768
#define NHEAD  12
#define DH     64
#define ROWS   (L_SEQ * NB)      // 8192
#define E3     (3 * EMB)         // 2304
#define E4     (4 * EMB)         // 3072

// ---------------- scratch (device globals: no allocation allowed) ----------------
__device__ float g_h   [ (size_t)ROWS * EMB ];   // LN1 out, reused for LN2 out
__device__ float g_qkv [ (size_t)ROWS * E3  ];   // QKV projection
__device__ float g_attn[ (size_t)ROWS * EMB ];   // attention output (pre out-proj)
__device__ float g_x1  [ (size_t)ROWS * EMB ];   // x + attn_out (first residual)
__device__ float g_f   [ (size_t)ROWS * E4  ];   // FC + QuickGELU activations

// ---------------- LayerNorm: one block per row (E = 768, 256 threads) ----------------
__global__ __launch_bounds__(256) void ln_kernel(const float* __restrict__ x,
                                                 const float* __restrict__ w,
                                                 const float* __restrict__ b,
                                                 float* __restrict__ out)
{
    int row = blockIdx.x;
    const float* xr = x + (size_t)row * EMB;
    float* orow = out + (size_t)row * EMB;
    int t = threadIdx.x;

    float v[3];
    float sum = 0.f, sq = 0.f;
#pragma unroll
    for (int i = 0; i < 3; i++) {
        v[i] = xr[t + 256 * i];
        sum += v[i];
        sq  += v[i] * v[i];
    }

    // block reduce (sum, sq)
    __shared__ float s1[8], s2[8], bc[2];
    for (int o = 16; o > 0; o >>= 1) {
        sum += __shfl_xor_sync(0xffffffffu, sum, o);
        sq  += __shfl_xor_sync(0xffffffffu, sq,  o);
    }
    int wid = t >> 5, lid = t & 31;
    if (lid == 0) { s1[wid] = sum; s2[wid] = sq; }
    __syncthreads();
    if (t == 0) {
        float ts = 0.f, tq = 0.f;
#pragma unroll
        for (int i = 0; i < 8; i++) { ts += s1[i]; tq += s2[i]; }
        float mu  = ts * (1.0f / EMB);
        float var = tq * (1.0f / EMB) - mu * mu;
        bc[0] = mu;
        bc[1] = rsqrtf(var + 1e-5f);
    }
    __syncthreads();
    float mu = bc[0], rstd = bc[1];
#pragma unroll
    for (int i = 0; i < 3; i++) {
        int c = t + 256 * i;
        orow[c] = (v[i] - mu) * rstd * w[c] + b[c];
    }
}

// ---------------- GEMM: C[M,N] = A[M,K] @ B[N,K]^T + bias (+epilogue) ----------------
// EPI 0: plain   EPI 1: + res   EPI 2: QuickGELU
template <int EPI>
__global__ __launch_bounds__(256) void gemm_kernel(
    const float* __restrict__ A, const float* __restrict__ B,
    const float* __restrict__ bias, const float* __restrict__ res,
    float* __restrict__ C, int M, int N, int K)
{
    __shared__ float As[16][68];   // [k][m], padded
    __shared__ float Bs[16][68];   // [k][n], padded

    int bm = blockIdx.y * 64;
    int bn = blockIdx.x * 64;
    int tid = threadIdx.x;
    int tm = (tid >> 4) * 4;       // 0..60
    int tn = (tid & 15) * 4;       // 0..60
    int lr = tid >> 2;             // 0..63  (tile row loaded)
    int lk = (tid & 3) * 4;        // 0,4,8,12

    const float* Aptr = A + (size_t)(bm + lr) * K + lk;
    const float* Bptr = B + (size_t)(bn + lr) * K + lk;

    float acc[4][4];
#pragma unroll
    for (int i = 0; i < 4; i++)
#pragma unroll
        for (int j = 0; j < 4; j++) acc[i][j] = 0.f;

    for (int k0 = 0; k0 < K; k0 += 16) {
        float4 av = *(const float4*)(Aptr + k0);
        float4 bv = *(const float4*)(Bptr + k0);
        As[lk + 0][lr] = av.x; As[lk + 1][lr] = av.y;
        As[lk + 2][lr] = av.z; As[lk + 3][lr] = av.w;
        Bs[lk + 0][lr] = bv.x; Bs[lk + 1][lr] = bv.y;
        Bs[lk + 2][lr] = bv.z; Bs[lk + 3][lr] = bv.w;
        __syncthreads();
#pragma unroll
        for (int kk = 0; kk < 16; kk++) {
            float4 a4 = *(const float4*)&As[kk][tm];
            float4 b4 = *(const float4*)&Bs[kk][tn];
            float a[4] = {a4.x, a4.y, a4.z, a4.w};
            float c[4] = {b4.x, b4.y, b4.z, b4.w};
#pragma unroll
            for (int i = 0; i < 4; i++)
#pragma unroll
                for (int j = 0; j < 4; j++)
                    acc[i][j] = fmaf(a[i], c[j], acc[i][j]);
        }
        __syncthreads();
    }

    float bvals[4];
#pragma unroll
    for (int j = 0; j < 4; j++) bvals[j] = bias[bn + tn + j];

#pragma unroll
    for (int i = 0; i < 4; i++) {
        size_t idx = (size_t)(bm + tm + i) * N + bn + tn;
        float o[4];
#pragma unroll
        for (int j = 0; j < 4; j++) {
            float c = acc[i][j] + bvals[j];
            if (EPI == 1) c += res[idx + j];
            if (EPI == 2) c = c / (1.f + __expf(-1.702f * c));
            o[j] = c;
        }
        float4 v = make_float4(o[0], o[1], o[2], o[3]);
        *(float4*)&C[idx] = v;
    }
}

// ---------------- Flash attention: 1 thread = 1 query row, Bc = 32 ----------------
// grid (L/128, H, N), 128 threads
__global__ __launch_bounds__(128) void flash_attn_kernel(const float* __restrict__ qkv,
                                                         float* __restrict__ o)
{
    __shared__ float Ks[32][68];
    __shared__ float Vs[32][68];

    int t = threadIdx.x;                  // 0..127
    int l = blockIdx.x * 128 + t;         // query position
    int h = blockIdx.y;
    int n = blockIdx.z;

    const float scale = 0.125f;           // 1/sqrt(64)
    float q[DH], O[DH], s[32];

    size_t qbase = ((size_t)l * NB + n) * E3 + h * DH;
#pragma unroll
    for (int d = 0; d < DH; d += 4) {
        float4 v = *(const float4*)&qkv[qbase + d];
        q[d] = v.x * scale; q[d + 1] = v.y * scale;
        q[d + 2] = v.z * scale; q[d + 3] = v.w * scale;
    }
#pragma unroll
    for (int d = 0; d < DH; d++) O[d] = 0.f;
    float m = -1e30f, lsum = 0.f;

    int jr = t >> 2;                       // 0..31: kv row this thread loads
    int c0 = (t & 3) * 16;                 // 16 floats each

    for (int kb = 0; kb < L_SEQ / 32; kb++) {
        size_t kbase = ((size_t)(kb * 32 + jr) * NB + n) * E3 + h * DH;
#pragma unroll
        for (int i = 0; i < 16; i += 4) {
            *(float4*)&Ks[jr][c0 + i] = *(const float4*)&qkv[kbase + EMB  + c0 + i];
            *(float4*)&Vs[jr][c0 + i] = *(const float4*)&qkv[kbase + 2*EMB + c0 + i];
        }
        __syncthreads();

        float mt = m;
#pragma unroll
        for (int jj = 0; jj < 32; jj++) {
            float acc = 0.f;
#pragma unroll
            for (int d = 0; d < DH; d += 4) {
                float4 kv = *(const float4*)&Ks[jj][d];   // broadcast LDS.128
                acc = fmaf(q[d], kv.x, acc);
                acc = fmaf(q[d + 1], kv.y, acc);
                acc = fmaf(q[d + 2], kv.z, acc);
                acc = fmaf(q[d + 3], kv.w, acc);
            }
            s[jj] = acc;
            mt = fmaxf(mt, acc);
        }
        float alpha = __expf(m - mt);
        m = mt;
        lsum *= alpha;
#pragma unroll
        for (int d = 0; d < DH; d++) O[d] *= alpha;

#pragma unroll
        for (int jj = 0; jj < 32; jj++) {
            float p = __expf(s[jj] - m);
            lsum += p;
#pragma unroll
            for (int d = 0; d < DH; d += 4) {
                float4 vv = *(const float4*)&Vs[jj][d];   // broadcast LDS.128
                O[d]     = fmaf(p, vv.x, O[d]);
                O[d + 1] = fmaf(p, vv.y, O[d + 1]);
                O[d + 2] = fmaf(p, vv.z, O[d + 2]);
                O[d + 3] = fmaf(p, vv.w, O[d + 3]);
            }
        }
        __syncthreads();
    }

    float inv = 1.f / lsum;
    size_t obase = ((size_t)l * NB + n) * EMB + h * DH;
#pragma unroll
    for (int d = 0; d < DH; d += 4) {
        float4 v = make_float4(O[d] * inv, O[d + 1] * inv, O[d + 2] * inv, O[d + 3] * inv);
        *(float4*)&o[obase + d] = v;
    }
}

// ---------------- launch ----------------
extern "C" void kernel_launch(void* const* d_in, const int* in_sizes, int n_in,
                              void* d_out, int out_size)
{
    const float* x      = (const float*)d_in[0];
    const float* ln1_w  = (const float*)d_in[1];
    const float* ln1_b  = (const float*)d_in[2];
    const float* w_qkv  = (const float*)d_in[3];
    const float* b_qkv  = (const float*)d_in[4];
    const float* w_out  = (const float*)d_in[5];
    const float* b_out  = (const float*)d_in[6];
    const float* ln2_w  = (const float*)d_in[7];
    const float* ln2_b  = (const float*)d_in[8];
    const float* w_fc   = (const float*)d_in[9];
    const float* b_fc   = (const float*)d_in[10];
    const float* w_proj = (const float*)d_in[11];
    const float* b_proj = (const float*)d_in[12];
    float* out = (float*)d_out;

    float *h, *qkv, *attn, *x1, *f;
    cudaGetSymbolAddress((void**)&h,    g_h);
    cudaGetSymbolAddress((void**)&qkv,  g_qkv);
    cudaGetSymbolAddress((void**)&attn, g_attn);
    cudaGetSymbolAddress((void**)&x1,   g_x1);
    cudaGetSymbolAddress((void**)&f,    g_f);

    // 1. LN1
    ln_kernel<<<ROWS, 256>>>(x, ln1_w, ln1_b, h);
    // 2. QKV projection: [8192,768] x [2304,768]^T
    gemm_kernel<0><<<dim3(E3 / 64, ROWS / 64), 256>>>(h, w_qkv, b_qkv, nullptr, qkv,
                                                      ROWS, E3, EMB);
    // 3. attention
    flash_attn_kernel<<<dim3(L_SEQ / 128, NHEAD, NB), 128>>>(qkv, attn);
    // 4. out-proj + residual: x1 = x + attn @ w_out^T + b_out
    gemm_kernel<1><<<dim3(EMB / 64, ROWS / 64), 256>>>(attn, w_out, b_out, x, x1,
                                                       ROWS, EMB, EMB);
    // 5. LN2 (reuse h)
    ln_kernel<<<ROWS, 256>>>(x1, ln2_w, ln2_b, h);
    // 6. FC + QuickGELU: f = gelu(h @ w_fc^T + b_fc)
    gemm_kernel<2><<<dim3(E4 / 64, ROWS / 64), 256>>>(h, w_fc, b_fc, nullptr, f,
                                                      ROWS, E4, EMB);
    // 7. proj + residual: out = x1 + f @ w_proj^T + b_proj
    gemm_kernel<1><<<dim3(EMB / 64, ROWS / 64), 256>>>(f, w_proj, b_proj, x1, out,
                                                       ROWS, EMB, E4);
}

// round 2
// speedup vs baseline: 1.0891x; 1.0891x over previous
#include <cuda_runtime.h>
#include <math.h>

#define L_SEQ  2048
#define NB     4
#define EMB    768
#define NHEAD  12
#define DH     64
#define ROWS   (L_SEQ * NB)      // 8192
#define E3     (3 * EMB)         // 2304
#define E4     (4 * EMB)         // 3072

// ---------------- scratch (device globals: no allocation allowed) ----------------
__device__ float g_h   [ (size_t)ROWS * EMB ];
__device__ float g_qkv [ (size_t)ROWS * E3  ];
__device__ float g_attn[ (size_t)ROWS * EMB ];
__device__ float g_x1  [ (size_t)ROWS * EMB ];
__device__ float g_f   [ (size_t)ROWS * E4  ];

// ---------------- LayerNorm: one block per row ----------------
__global__ __launch_bounds__(256) void ln_kernel(const float* __restrict__ x,
                                                 const float* __restrict__ w,
                                                 const float* __restrict__ b,
                                                 float* __restrict__ out)
{
    int row = blockIdx.x;
    const float* xr = x + (size_t)row * EMB;
    float* orow = out + (size_t)row * EMB;
    int t = threadIdx.x;

    float v[3];
    float sum = 0.f, sq = 0.f;
#pragma unroll
    for (int i = 0; i < 3; i++) {
        v[i] = xr[t + 256 * i];
        sum += v[i];
        sq  += v[i] * v[i];
    }
    __shared__ float s1[8], s2[8], bc[2];
    for (int o = 16; o > 0; o >>= 1) {
        sum += __shfl_xor_sync(0xffffffffu, sum, o);
        sq  += __shfl_xor_sync(0xffffffffu, sq,  o);
    }
    int wid = t >> 5, lid = t & 31;
    if (lid == 0) { s1[wid] = sum; s2[wid] = sq; }
    __syncthreads();
    if (t == 0) {
        float ts = 0.f, tq = 0.f;
#pragma unroll
        for (int i = 0; i < 8; i++) { ts += s1[i]; tq += s2[i]; }
        float mu  = ts * (1.0f / EMB);
        float var = tq * (1.0f / EMB) - mu * mu;
        bc[0] = mu;
        bc[1] = rsqrtf(var + 1e-5f);
    }
    __syncthreads();
    float mu = bc[0], rstd = bc[1];
#pragma unroll
    for (int i = 0; i < 3; i++) {
        int c = t + 256 * i;
        orow[c] = (v[i] - mu) * rstd * w[c] + b[c];
    }
}

// ---------------- GEMM: C[M,N] = A[M,K] @ B[N,K]^T + bias (+epilogue) ----------------
// 128x128x16 tile, 256 threads, 8x8 micro-tile, double-buffered smem.
// EPI 0: plain   EPI 1: + res   EPI 2: QuickGELU
#define BM 128
#define BN 128
#define BK 16

template <int EPI>
__global__ __launch_bounds__(256) void gemm_kernel(
    const float* __restrict__ A, const float* __restrict__ B,
    const float* __restrict__ bias, const float* __restrict__ res,
    float* __restrict__ C, int M, int N, int K)
{
    __shared__ float As[2][BK][BM + 4];   // [k][m]
    __shared__ float Bs[2][BK][BN + 4];   // [k][n]

    int bm = blockIdx.y * BM;
    int bn = blockIdx.x * BN;
    int tid = threadIdx.x;
    int tm = (tid >> 4) * 8;       // 0..120
    int tn = (tid & 15) * 8;       // 0..120
    int lr = tid >> 1;             // 0..127 : tile row loaded
    int lc = (tid & 1) * 8;        // 0 or 8 : k offset loaded

    const float* Ap = A + (size_t)(bm + lr) * K + lc;
    const float* Bp = B + (size_t)(bn + lr) * K + lc;

    float acc[8][8];
#pragma unroll
    for (int i = 0; i < 8; i++)
#pragma unroll
        for (int j = 0; j < 8; j++) acc[i][j] = 0.f;

    // ---- preload tile 0 into buffer 0 ----
    {
        float4 a0 = *(const float4*)(Ap);
        float4 a1 = *(const float4*)(Ap + 4);
        float4 b0 = *(const float4*)(Bp);
        float4 b1 = *(const float4*)(Bp + 4);
        As[0][lc + 0][lr] = a0.x; As[0][lc + 1][lr] = a0.y;
        As[0][lc + 2][lr] = a0.z; As[0][lc + 3][lr] = a0.w;
        As[0][lc + 4][lr] = a1.x; As[0][lc + 5][lr] = a1.y;
        As[0][lc + 6][lr] = a1.z; As[0][lc + 7][lr] = a1.w;
        Bs[0][lc + 0][lr] = b0.x; Bs[0][lc + 1][lr] = b0.y;
        Bs[0][lc + 2][lr] = b0.z; Bs[0][lc + 3][lr] = b0.w;
        Bs[0][lc + 4][lr] = b1.x; Bs[0][lc + 5][lr] = b1.y;
        Bs[0][lc + 6][lr] = b1.z; Bs[0][lc + 7][lr] = b1.w;
    }
    __syncthreads();

    int s = 0;
    for (int k0 = BK; k0 <= K; k0 += BK) {
        // prefetch next tile into registers
        float4 a0, a1, b0, b1;
        bool more = (k0 < K);
        if (more) {
            a0 = *(const float4*)(Ap + k0);
            a1 = *(const float4*)(Ap + k0 + 4);
            b0 = *(const float4*)(Bp + k0);
            b1 = *(const float4*)(Bp + k0 + 4);
        }
        // compute on buffer s
#pragma unroll
        for (int kk = 0; kk < BK; kk++) {
            float4 av0 = *(const float4*)&As[s][kk][tm];
            float4 av1 = *(const float4*)&As[s][kk][tm + 4];
            float4 bv0 = *(const float4*)&Bs[s][kk][tn];
            float4 bv1 = *(const float4*)&Bs[s][kk][tn + 4];
            float a[8] = {av0.x, av0.y, av0.z, av0.w, av1.x, av1.y, av1.z, av1.w};
            float b[8] = {bv0.x, bv0.y, bv0.z, bv0.w, bv1.x, bv1.y, bv1.z, bv1.w};
#pragma unroll
            for (int i = 0; i < 8; i++)
#pragma unroll
                for (int j = 0; j < 8; j++)
                    acc[i][j] = fmaf(a[i], b[j], acc[i][j]);
        }
        if (more) {
            int ns = s ^ 1;
            As[ns][lc + 0][lr] = a0.x; As[ns][lc + 1][lr] = a0.y;
            As[ns][lc + 2][lr] = a0.z; As[ns][lc + 3][lr] = a0.w;
            As[ns][lc + 4][lr] = a1.x; As[ns][lc + 5][lr] = a1.y;
            As[ns][lc + 6][lr] = a1.z; As[ns][lc + 7][lr] = a1.w;
            Bs[ns][lc + 0][lr] = b0.x; Bs[ns][lc + 1][lr] = b0.y;
            Bs[ns][lc + 2][lr] = b0.z; Bs[ns][lc + 3][lr] = b0.w;
            Bs[ns][lc + 4][lr] = b1.x; Bs[ns][lc + 5][lr] = b1.y;
            Bs[ns][lc + 6][lr] = b1.z; Bs[ns][lc + 7][lr] = b1.w;
            __syncthreads();
            s = ns;
        }
    }

    float bv[8];
#pragma unroll
    for (int j = 0; j < 8; j++) bv[j] = bias[bn + tn + j];

#pragma unroll
    for (int i = 0; i < 8; i++) {
        size_t idx = (size_t)(bm + tm + i) * N + bn + tn;
        float o[8];
#pragma unroll
        for (int j = 0; j < 8; j++) {
            float c = acc[i][j] + bv[j];
            if (EPI == 1) c += res[idx + j];
            if (EPI == 2) c = c / (1.f + __expf(-1.702f * c));
            o[j] = c;
        }
        *(float4*)&C[idx]     = make_float4(o[0], o[1], o[2], o[3]);
        *(float4*)&C[idx + 4] = make_float4(o[4], o[5], o[6], o[7]);
    }
}

// ---------------- Flash attention: 1 thread = 1 query row, Bc = 32 ----------------
__global__ __launch_bounds__(128) void flash_attn_kernel(const float* __restrict__ qkv,
                                                         float* __restrict__ o)
{
    __shared__ float Ks[32][68];
    __shared__ float Vs[32][68];

    int t = threadIdx.x;
    int l = blockIdx.x * 128 + t;
    int h = blockIdx.y;
    int n = blockIdx.z;

    const float scale = 0.125f;
    float q[DH], O[DH], s[32];

    size_t qbase = ((size_t)l * NB + n) * E3 + h * DH;
#pragma unroll
    for (int d = 0; d < DH; d += 4) {
        float4 v = *(const float4*)&qkv[qbase + d];
        q[d] = v.x * scale; q[d + 1] = v.y * scale;
        q[d + 2] = v.z * scale; q[d + 3] = v.w * scale;
    }
#pragma unroll
    for (int d = 0; d < DH; d++) O[d] = 0.f;
    float m = -1e30f, lsum = 0.f;

    int jr = t >> 2;
    int c0 = (t & 3) * 16;

    for (int kb = 0; kb < L_SEQ / 32; kb++) {
        size_t kbase = ((size_t)(kb * 32 + jr) * NB + n) * E3 + h * DH;
#pragma unroll
        for (int i = 0; i < 16; i += 4) {
            *(float4*)&Ks[jr][c0 + i] = *(const float4*)&qkv[kbase + EMB   + c0 + i];
            *(float4*)&Vs[jr][c0 + i] = *(const float4*)&qkv[kbase + 2*EMB + c0 + i];
        }
        __syncthreads();

        float mt = m;
#pragma unroll
        for (int jj = 0; jj < 32; jj++) {
            float acc = 0.f;
#pragma unroll
            for (int d = 0; d < DH; d += 4) {
                float4 kv = *(const float4*)&Ks[jj][d];
                acc = fmaf(q[d], kv.x, acc);
                acc = fmaf(q[d + 1], kv.y, acc);
                acc = fmaf(q[d + 2], kv.z, acc);
                acc = fmaf(q[d + 3], kv.w, acc);
            }
            s[jj] = acc;
            mt = fmaxf(mt, acc);
        }
        float alpha = __expf(m - mt);
        m = mt;
        lsum *= alpha;
#pragma unroll
        for (int d = 0; d < DH; d++) O[d] *= alpha;

#pragma unroll
        for (int jj = 0; jj < 32; jj++) {
            float p = __expf(s[jj] - m);
            lsum += p;
#pragma unroll
            for (int d = 0; d < DH; d += 4) {
                float4 vv = *(const float4*)&Vs[jj][d];
                O[d]     = fmaf(p, vv.x, O[d]);
                O[d + 1] = fmaf(p, vv.y, O[d + 1]);
                O[d + 2] = fmaf(p, vv.z, O[d + 2]);
                O[d + 3] = fmaf(p, vv.w, O[d + 3]);
            }
        }
        __syncthreads();
    }

    float inv = 1.f / lsum;
    size_t obase = ((size_t)l * NB + n) * EMB + h * DH;
#pragma unroll
    for (int d = 0; d < DH; d += 4) {
        float4 v = make_float4(O[d] * inv, O[d + 1] * inv, O[d + 2] * inv, O[d + 3] * inv);
        *(float4*)&o[obase + d] = v;
    }
}

// ---------------- launch ----------------
extern "C" void kernel_launch(void* const* d_in, const int* in_sizes, int n_in,
                              void* d_out, int out_size)
{
    const float* x      = (const float*)d_in[0];
    const float* ln1_w  = (const float*)d_in[1];
    const float* ln1_b  = (const float*)d_in[2];
    const float* w_qkv  = (const float*)d_in[3];
    const float* b_qkv  = (const float*)d_in[4];
    const float* w_out  = (const float*)d_in[5];
    const float* b_out  = (const float*)d_in[6];
    const float* ln2_w  = (const float*)d_in[7];
    const float* ln2_b  = (const float*)d_in[8];
    const float* w_fc   = (const float*)d_in[9];
    const float* b_fc   = (const float*)d_in[10];
    const float* w_proj = (const float*)d_in[11];
    const float* b_proj = (const float*)d_in[12];
    float* out = (float*)d_out;

    float *h, *qkv, *attn, *x1, *f;
    cudaGetSymbolAddress((void**)&h,    g_h);
    cudaGetSymbolAddress((void**)&qkv,  g_qkv);
    cudaGetSymbolAddress((void**)&attn, g_attn);
    cudaGetSymbolAddress((void**)&x1,   g_x1);
    cudaGetSymbolAddress((void**)&f,    g_f);

    ln_kernel<<<ROWS, 256>>>(x, ln1_w, ln1_b, h);
    gemm_kernel<0><<<dim3(E3 / BN, ROWS / BM), 256>>>(h, w_qkv, b_qkv, nullptr, qkv,
                                                      ROWS, E3, EMB);
    flash_attn_kernel<<<dim3(L_SEQ / 128, NHEAD, NB), 128>>>(qkv, attn);
    gemm_kernel<1><<<dim3(EMB / BN, ROWS / BM), 256>>>(attn, w_out, b_out, x, x1,
                                                       ROWS, EMB, EMB);
    ln_kernel<<<ROWS, 256>>>(x1, ln2_w, ln2_b, h);
    gemm_kernel<2><<<dim3(E4 / BN, ROWS / BM), 256>>>(h, w_fc, b_fc, nullptr, f,
                                                      ROWS, E4, EMB);
    gemm_kernel<1><<<dim3(EMB / BN, ROWS / BM), 256>>>(f, w_proj, b_proj, x1, out,
                                                       ROWS, EMB, E4);
}

// round 4
// speedup vs baseline: 1.3860x; 1.2725x over previous
#include <cuda_runtime.h>
#include <mma.h>
#include <math.h>
#include <stdint.h>

using namespace nvcuda;

#define L_SEQ  2048
#define NB     4
#define EMB    768
#define NHEAD  12
#define DH     64
#define ROWS   (L_SEQ * NB)      // 8192
#define E3     (3 * EMB)         // 2304
#define E4     (4 * EMB)         // 3072

// ---------------- scratch ----------------
__device__ float g_h   [ (size_t)ROWS * EMB ];
__device__ float g_qkv [ (size_t)ROWS * E3  ];
__device__ float g_attn[ (size_t)ROWS * EMB ];
__device__ float g_x1  [ (size_t)ROWS * EMB ];
__device__ float g_f   [ (size_t)ROWS * E4  ];

#define CVT_TF32(d, s) asm volatile("cvt.rna.tf32.f32 %0, %1;" : "=r"(d) : "f"(s))

// ---------------- LayerNorm ----------------
__global__ __launch_bounds__(256) void ln_kernel(const float* __restrict__ x,
                                                 const float* __restrict__ w,
                                                 const float* __restrict__ b,
                                                 float* __restrict__ out)
{
    int row = blockIdx.x;
    const float* xr = x + (size_t)row * EMB;
    float* orow = out + (size_t)row * EMB;
    int t = threadIdx.x;

    float v[3];
    float sum = 0.f, sq = 0.f;
#pragma unroll
    for (int i = 0; i < 3; i++) {
        v[i] = xr[t + 256 * i];
        sum += v[i];
        sq  += v[i] * v[i];
    }
    __shared__ float s1[8], s2[8], bc[2];
    for (int o = 16; o > 0; o >>= 1) {
        sum += __shfl_xor_sync(0xffffffffu, sum, o);
        sq  += __shfl_xor_sync(0xffffffffu, sq,  o);
    }
    int wid = t >> 5, lid = t & 31;
    if (lid == 0) { s1[wid] = sum; s2[wid] = sq; }
    __syncthreads();
    if (t == 0) {
        float ts = 0.f, tq = 0.f;
#pragma unroll
        for (int i = 0; i < 8; i++) { ts += s1[i]; tq += s2[i]; }
        float mu  = ts * (1.0f / EMB);
        float var = tq * (1.0f / EMB) - mu * mu;
        bc[0] = mu;
        bc[1] = rsqrtf(var + 1e-5f);
    }
    __syncthreads();
    float mu = bc[0], rstd = bc[1];
#pragma unroll
    for (int i = 0; i < 3; i++) {
        int c = t + 256 * i;
        orow[c] = (v[i] - mu) * rstd * w[c] + b[c];
    }
}

// ---------------- WMMA tf32 GEMM: C[M,N] = A[M,K] @ B[N,K]^T + bias (+EPI) ----------------
// 128x128 block tile, BK=16, double buffer, 8 warps (2x4), 64x32 warp tile.
// EPI 0: plain  1: +res  2: QuickGELU
#define BKG  16
#define LDS_ 20                       // padded row (floats)
#define ABUF_FLOATS (2 * 128 * LDS_)  // per operand, both buffers
#define GT_SMEM (2 * ABUF_FLOATS * 4) // 40960 bytes

template <int EPI>
__global__ __launch_bounds__(256) void gemm_wmma(
    const float* __restrict__ A, const float* __restrict__ B,
    const float* __restrict__ bias, const float* __restrict__ res,
    float* __restrict__ C, int M, int N, int K)
{
    extern __shared__ float smem[];
    float* As = smem;                       // [2][128][LDS_]
    float* Bs = smem + ABUF_FLOATS;         // [2][128][LDS_]
    float* epi = smem;                      // overlay after main loop: [8][16][LDS_]

    const int tid  = threadIdx.x;
    const int wid  = tid >> 5;
    const int lane = tid & 31;

    const int bm = blockIdx.y * 128;
    const int bn = blockIdx.x * 128;
    const int wm = (wid >> 2) * 64;         // warp row offset in tile
    const int wn = (wid & 3) * 32;          // warp col offset in tile

    // staging: 256 threads, each loads 8 floats of A and 8 of B per chunk
    const int lr = tid >> 1;                // 0..127
    const int lk = (tid & 1) * 8;           // 0 or 8
    const float* Ap = A + (size_t)(bm + lr) * K + lk;
    const float* Bp = B + (size_t)(bn + lr) * K + lk;

    wmma::fragment<wmma::accumulator, 16, 16, 8, float> acc[4][2];
#pragma unroll
    for (int i = 0; i < 4; i++)
#pragma unroll
        for (int j = 0; j < 2; j++) wmma::fill_fragment(acc[i][j], 0.f);

    // preload chunk 0 -> buffer 0 (convert to tf32 bits at staging)
    {
        float4 a0 = *(const float4*)(Ap);
        float4 a1 = *(const float4*)(Ap + 4);
        float4 b0 = *(const float4*)(Bp);
        float4 b1 = *(const float4*)(Bp + 4);
        uint32_t* as = (uint32_t*)&As[lr * LDS_ + lk];
        uint32_t* bs = (uint32_t*)&Bs[lr * LDS_ + lk];
        CVT_TF32(as[0], a0.x); CVT_TF32(as[1], a0.y); CVT_TF32(as[2], a0.z); CVT_TF32(as[3], a0.w);
        CVT_TF32(as[4], a1.x); CVT_TF32(as[5], a1.y); CVT_TF32(as[6], a1.z); CVT_TF32(as[7], a1.w);
        CVT_TF32(bs[0], b0.x); CVT_TF32(bs[1], b0.y); CVT_TF32(bs[2], b0.z); CVT_TF32(bs[3], b0.w);
        CVT_TF32(bs[4], b1.x); CVT_TF32(bs[5], b1.y); CVT_TF32(bs[6], b1.z); CVT_TF32(bs[7], b1.w);
    }
    __syncthreads();

    const int NC = K / BKG;
    for (int c = 0; c < NC; c++) {
        int s = c & 1;
        float4 a0, a1, b0, b1;
        bool more = (c + 1 < NC);
        if (more) {
            const float* Apc = Ap + (size_t)(c + 1) * BKG;
            const float* Bpc = Bp + (size_t)(c + 1) * BKG;
            a0 = *(const float4*)(Apc);
            a1 = *(const float4*)(Apc + 4);
            b0 = *(const float4*)(Bpc);
            b1 = *(const float4*)(Bpc + 4);
        }

        const float* Asb = As + s * 128 * LDS_;
        const float* Bsb = Bs + s * 128 * LDS_;
#pragma unroll
        for (int kk = 0; kk < BKG; kk += 8) {
            wmma::fragment<wmma::matrix_a, 16, 16, 8, wmma::precision::tf32, wmma::row_major> af[4];
            wmma::fragment<wmma::matrix_b, 16, 16, 8, wmma::precision::tf32, wmma::col_major> bf[2];
#pragma unroll
            for (int i = 0; i < 4; i++)
                wmma::load_matrix_sync(af[i], Asb + (wm + i * 16) * LDS_ + kk, LDS_);
#pragma unroll
            for (int j = 0; j < 2; j++)
                wmma::load_matrix_sync(bf[j], Bsb + (wn + j * 16) * LDS_ + kk, LDS_);
#pragma unroll
            for (int i = 0; i < 4; i++)
#pragma unroll
                for (int j = 0; j < 2; j++)
                    wmma::mma_sync(acc[i][j], af[i], bf[j], acc[i][j]);
        }

        if (more) {
            int ns = s ^ 1;
            uint32_t* as = (uint32_t*)&As[ns * 128 * LDS_ + lr * LDS_ + lk];
            uint32_t* bs = (uint32_t*)&Bs[ns * 128 * LDS_ + lr * LDS_ + lk];
            CVT_TF32(as[0], a0.x); CVT_TF32(as[1], a0.y); CVT_TF32(as[2], a0.z); CVT_TF32(as[3], a0.w);
            CVT_TF32(as[4], a1.x); CVT_TF32(as[5], a1.y); CVT_TF32(as[6], a1.z); CVT_TF32(as[7], a1.w);
            CVT_TF32(bs[0], b0.x); CVT_TF32(bs[1], b0.y); CVT_TF32(bs[2], b0.z); CVT_TF32(bs[3], b0.w);
            CVT_TF32(bs[4], b1.x); CVT_TF32(bs[5], b1.y); CVT_TF32(bs[6], b1.z); CVT_TF32(bs[7], b1.w);
            __syncthreads();
        }
    }
    __syncthreads();   // all compute done; epi overlays As

    // epilogue: per warp, drain 8 accumulator frags through smem scratch
    float* ep = epi + wid * 16 * LDS_;
#pragma unroll
    for (int fm = 0; fm < 4; fm++) {
#pragma unroll
        for (int fn = 0; fn < 2; fn++) {
            wmma::store_matrix_sync(ep, acc[fm][fn], LDS_, wmma::mem_row_major);
            __syncwarp();
            int r  = lane >> 1;
            int c8 = (lane & 1) * 8;
            int grow = bm + wm + fm * 16 + r;
            int gcol = bn + wn + fn * 16 + c8;
            size_t gidx = (size_t)grow * N + gcol;
            float o[8];
#pragma unroll
            for (int q = 0; q < 8; q++) {
                float cv = ep[r * LDS_ + c8 + q] + bias[gcol + q];
                if (EPI == 1) cv += res[gidx + q];
                if (EPI == 2) cv = cv / (1.f + __expf(-1.702f * cv));
                o[q] = cv;
            }
            *(float4*)&C[gidx]     = make_float4(o[0], o[1], o[2], o[3]);
            *(float4*)&C[gidx + 4] = make_float4(o[4], o[5], o[6], o[7]);
            __syncwarp();
        }
    }
}

// ---------------- Flash attention: 1 thread = 1 query row, Bc = 32 ----------------
__global__ __launch_bounds__(128) void flash_attn_kernel(const float* __restrict__ qkv,
                                                         float* __restrict__ o)
{
    __shared__ float Ks[32][68];
    __shared__ float Vs[32][68];

    int t = threadIdx.x;
    int l = blockIdx.x * 128 + t;
    int h = blockIdx.y;
    int n = blockIdx.z;

    const float scale = 0.125f;
    float q[DH], O[DH], s[32];

    size_t qbase = ((size_t)l * NB + n) * E3 + h * DH;
#pragma unroll
    for (int d = 0; d < DH; d += 4) {
        float4 v = *(const float4*)&qkv[qbase + d];
        q[d] = v.x * scale; q[d + 1] = v.y * scale;
        q[d + 2] = v.z * scale; q[d + 3] = v.w * scale;
    }
#pragma unroll
    for (int d = 0; d < DH; d++) O[d] = 0.f;
    float m = -1e30f, lsum = 0.f;

    int jr = t >> 2;
    int c0 = (t & 3) * 16;

    for (int kb = 0; kb < L_SEQ / 32; kb++) {
        size_t kbase = ((size_t)(kb * 32 + jr) * NB + n) * E3 + h * DH;
#pragma unroll
        for (int i = 0; i < 16; i += 4) {
            *(float4*)&Ks[jr][c0 + i] = *(const float4*)&qkv[kbase + EMB   + c0 + i];
            *(float4*)&Vs[jr][c0 + i] = *(const float4*)&qkv[kbase + 2*EMB + c0 + i];
        }
        __syncthreads();

        float mt = m;
#pragma unroll
        for (int jx = 0; jx < 32; jx++) {
            float acc = 0.f;
#pragma unroll
            for (int d = 0; d < DH; d += 4) {
                float4 kv = *(const float4*)&Ks[jx][d];
                acc = fmaf(q[d], kv.x, acc);
                acc = fmaf(q[d + 1], kv.y, acc);
                acc = fmaf(q[d + 2], kv.z, acc);
                acc = fmaf(q[d + 3], kv.w, acc);
            }
            s[jx] = acc;
            mt = fmaxf(mt, acc);
        }
        float alpha = __expf(m - mt);
        m = mt;
        lsum *= alpha;
#pragma unroll
        for (int d = 0; d < DH; d++) O[d] *= alpha;

#pragma unroll
        for (int jx = 0; jx < 32; jx++) {
            float p = __expf(s[jx] - m);
            lsum += p;
#pragma unroll
            for (int d = 0; d < DH; d += 4) {
                float4 vv = *(const float4*)&Vs[jx][d];
                O[d]     = fmaf(p, vv.x, O[d]);
                O[d + 1] = fmaf(p, vv.y, O[d + 1]);
                O[d + 2] = fmaf(p, vv.z, O[d + 2]);
                O[d + 3] = fmaf(p, vv.w, O[d + 3]);
            }
        }
        __syncthreads();
    }

    float inv = 1.f / lsum;
    size_t obase = ((size_t)l * NB + n) * EMB + h * DH;
#pragma unroll
    for (int d = 0; d < DH; d += 4) {
        float4 v = make_float4(O[d] * inv, O[d + 1] * inv, O[d + 2] * inv, O[d + 3] * inv);
        *(float4*)&o[obase + d] = v;
    }
}

// ---------------- launch ----------------
extern "C" void kernel_launch(void* const* d_in, const int* in_sizes, int n_in,
                              void* d_out, int out_size)
{
    const float* x      = (const float*)d_in[0];
    const float* ln1_w  = (const float*)d_in[1];
    const float* ln1_b  = (const float*)d_in[2];
    const float* w_qkv  = (const float*)d_in[3];
    const float* b_qkv  = (const float*)d_in[4];
    const float* w_out  = (const float*)d_in[5];
    const float* b_out  = (const float*)d_in[6];
    const float* ln2_w  = (const float*)d_in[7];
    const float* ln2_b  = (const float*)d_in[8];
    const float* w_fc   = (const float*)d_in[9];
    const float* b_fc   = (const float*)d_in[10];
    const float* w_proj = (const float*)d_in[11];
    const float* b_proj = (const float*)d_in[12];
    float* out = (float*)d_out;

    float *h, *qkv, *attn, *x1, *f;
    cudaGetSymbolAddress((void**)&h,    g_h);
    cudaGetSymbolAddress((void**)&qkv,  g_qkv);
    cudaGetSymbolAddress((void**)&attn, g_attn);
    cudaGetSymbolAddress((void**)&x1,   g_x1);
    cudaGetSymbolAddress((void**)&f,    g_f);

    cudaFuncSetAttribute(gemm_wmma<0>, cudaFuncAttributeMaxDynamicSharedMemorySize, GT_SMEM);
    cudaFuncSetAttribute(gemm_wmma<1>, cudaFuncAttributeMaxDynamicSharedMemorySize, GT_SMEM);
    cudaFuncSetAttribute(gemm_wmma<2>, cudaFuncAttributeMaxDynamicSharedMemorySize, GT_SMEM);

    ln_kernel<<<ROWS, 256>>>(x, ln1_w, ln1_b, h);
    gemm_wmma<0><<<dim3(E3 / 128, ROWS / 128), 256, GT_SMEM>>>(h, w_qkv, b_qkv, nullptr, qkv,
                                                               ROWS, E3, EMB);
    flash_attn_kernel<<<dim3(L_SEQ / 128, NHEAD, NB), 128>>>(qkv, attn);
    gemm_wmma<1><<<dim3(EMB / 128, ROWS / 128), 256, GT_SMEM>>>(attn, w_out, b_out, x, x1,
                                                                ROWS, EMB, EMB);
    ln_kernel<<<ROWS, 256>>>(x1, ln2_w, ln2_b, h);
    gemm_wmma<2><<<dim3(E4 / 128, ROWS / 128), 256, GT_SMEM>>>(h, w_fc, b_fc, nullptr, f,
                                                               ROWS, E4, EMB);
    gemm_wmma<1><<<dim3(EMB / 128, ROWS / 128), 256, GT_SMEM>>>(f, w_proj, b_proj, x1, out,
                                                                ROWS, EMB, E4);
}

// round 6
// speedup vs baseline: 1.9928x; 1.4379x over previous
#include <cuda_runtime.h>
#include <mma.h>
#include <math.h>
#include <stdint.h>

using namespace nvcuda;

#define L_SEQ  2048
#define NB     4
#define EMB    768
#define NHEAD  12
#define DH     64
#define ROWS   (L_SEQ * NB)      // 8192
#define E3     (3 * EMB)         // 2304
#define E4     (4 * EMB)         // 3072

// ---------------- scratch ----------------
__device__ float g_h   [ (size_t)ROWS * EMB ];
__device__ float g_qkv [ (size_t)ROWS * E3  ];
__device__ float g_attn[ (size_t)ROWS * EMB ];
__device__ float g_x1  [ (size_t)ROWS * EMB ];
__device__ float g_f   [ (size_t)ROWS * E4  ];

#define CVT_TF32(d, s) asm volatile("cvt.rna.tf32.f32 %0, %1;" : "=r"(d) : "f"(s))

__device__ __forceinline__ float ex2f(float x) {
    float y; asm("ex2.approx.f32 %0, %1;" : "=f"(y) : "f"(x)); return y;
}
__device__ __forceinline__ void mma8(float* c, const uint32_t* a, uint32_t b0, uint32_t b1) {
    asm volatile(
        "mma.sync.aligned.m16n8k8.row.col.f32.tf32.tf32.f32 "
        "{%0,%1,%2,%3}, {%4,%5,%6,%7}, {%8,%9}, {%0,%1,%2,%3};"
        : "+f"(c[0]), "+f"(c[1]), "+f"(c[2]), "+f"(c[3])
        : "r"(a[0]), "r"(a[1]), "r"(a[2]), "r"(a[3]), "r"(b0), "r"(b1));
}

// ---------------- LayerNorm ----------------
__global__ __launch_bounds__(256) void ln_kernel(const float* __restrict__ x,
                                                 const float* __restrict__ w,
                                                 const float* __restrict__ b,
                                                 float* __restrict__ out)
{
    int row = blockIdx.x;
    const float* xr = x + (size_t)row * EMB;
    float* orow = out + (size_t)row * EMB;
    int t = threadIdx.x;

    float v[3];
    float sum = 0.f, sq = 0.f;
#pragma unroll
    for (int i = 0; i < 3; i++) {
        v[i] = xr[t + 256 * i];
        sum += v[i];
        sq  += v[i] * v[i];
    }
    __shared__ float s1[8], s2[8], bc[2];
    for (int o = 16; o > 0; o >>= 1) {
        sum += __shfl_xor_sync(0xffffffffu, sum, o);
        sq  += __shfl_xor_sync(0xffffffffu, sq,  o);
    }
    int wid = t >> 5, lid = t & 31;
    if (lid == 0) { s1[wid] = sum; s2[wid] = sq; }
    __syncthreads();
    if (t == 0) {
        float ts = 0.f, tq = 0.f;
#pragma unroll
        for (int i = 0; i < 8; i++) { ts += s1[i]; tq += s2[i]; }
        float mu  = ts * (1.0f / EMB);
        float var = tq * (1.0f / EMB) - mu * mu;
        bc[0] = mu;
        bc[1] = rsqrtf(var + 1e-5f);
    }
    __syncthreads();
    float mu = bc[0], rstd = bc[1];
#pragma unroll
    for (int i = 0; i < 3; i++) {
        int c = t + 256 * i;
        orow[c] = (v[i] - mu) * rstd * w[c] + b[c];
    }
}

// ---------------- WMMA tf32 GEMM (unchanged from R4) ----------------
#define BKG  16
#define LDS_ 20
#define ABUF_FLOATS (2 * 128 * LDS_)
#define GT_SMEM (2 * ABUF_FLOATS * 4)

template <int EPI>
__global__ __launch_bounds__(256) void gemm_wmma(
    const float* __restrict__ A, const float* __restrict__ B,
    const float* __restrict__ bias, const float* __restrict__ res,
    float* __restrict__ C, int M, int N, int K)
{
    extern __shared__ float smem[];
    float* As = smem;
    float* Bs = smem + ABUF_FLOATS;
    float* epi = smem;

    const int tid  = threadIdx.x;
    const int wid  = tid >> 5;
    const int lane = tid & 31;

    const int bm = blockIdx.y * 128;
    const int bn = blockIdx.x * 128;
    const int wm = (wid >> 2) * 64;
    const int wn = (wid & 3) * 32;

    const int lr = tid >> 1;
    const int lk = (tid & 1) * 8;
    const float* Ap = A + (size_t)(bm + lr) * K + lk;
    const float* Bp = B + (size_t)(bn + lr) * K + lk;

    wmma::fragment<wmma::accumulator, 16, 16, 8, float> acc[4][2];
#pragma unroll
    for (int i = 0; i < 4; i++)
#pragma unroll
        for (int j = 0; j < 2; j++) wmma::fill_fragment(acc[i][j], 0.f);

    {
        float4 a0 = *(const float4*)(Ap);
        float4 a1 = *(const float4*)(Ap + 4);
        float4 b0 = *(const float4*)(Bp);
        float4 b1 = *(const float4*)(Bp + 4);
        uint32_t* as = (uint32_t*)&As[lr * LDS_ + lk];
        uint32_t* bs = (uint32_t*)&Bs[lr * LDS_ + lk];
        CVT_TF32(as[0], a0.x); CVT_TF32(as[1], a0.y); CVT_TF32(as[2], a0.z); CVT_TF32(as[3], a0.w);
        CVT_TF32(as[4], a1.x); CVT_TF32(as[5], a1.y); CVT_TF32(as[6], a1.z); CVT_TF32(as[7], a1.w);
        CVT_TF32(bs[0], b0.x); CVT_TF32(bs[1], b0.y); CVT_TF32(bs[2], b0.z); CVT_TF32(bs[3], b0.w);
        CVT_TF32(bs[4], b1.x); CVT_TF32(bs[5], b1.y); CVT_TF32(bs[6], b1.z); CVT_TF32(bs[7], b1.w);
    }
    __syncthreads();

    const int NC = K / BKG;
    for (int c = 0; c < NC; c++) {
        int s = c & 1;
        float4 a0, a1, b0, b1;
        bool more = (c + 1 < NC);
        if (more) {
            const float* Apc = Ap + (size_t)(c + 1) * BKG;
            const float* Bpc = Bp + (size_t)(c + 1) * BKG;
            a0 = *(const float4*)(Apc);
            a1 = *(const float4*)(Apc + 4);
            b0 = *(const float4*)(Bpc);
            b1 = *(const float4*)(Bpc + 4);
        }

        const float* Asb = As + s * 128 * LDS_;
        const float* Bsb = Bs + s * 128 * LDS_;
#pragma unroll
        for (int kk = 0; kk < BKG; kk += 8) {
            wmma::fragment<wmma::matrix_a, 16, 16, 8, wmma::precision::tf32, wmma::row_major> af[4];
            wmma::fragment<wmma::matrix_b, 16, 16, 8, wmma::precision::tf32, wmma::col_major> bf[2];
#pragma unroll
            for (int i = 0; i < 4; i++)
                wmma::load_matrix_sync(af[i], Asb + (wm + i * 16) * LDS_ + kk, LDS_);
#pragma unroll
            for (int j = 0; j < 2; j++)
                wmma::load_matrix_sync(bf[j], Bsb + (wn + j * 16) * LDS_ + kk, LDS_);
#pragma unroll
            for (int i = 0; i < 4; i++)
#pragma unroll
                for (int j = 0; j < 2; j++)
                    wmma::mma_sync(acc[i][j], af[i], bf[j], acc[i][j]);
        }

        if (more) {
            int ns = s ^ 1;
            uint32_t* as = (uint32_t*)&As[ns * 128 * LDS_ + lr * LDS_ + lk];
            uint32_t* bs = (uint32_t*)&Bs[ns * 128 * LDS_ + lr * LDS_ + lk];
            CVT_TF32(as[0], a0.x); CVT_TF32(as[1], a0.y); CVT_TF32(as[2], a0.z); CVT_TF32(as[3], a0.w);
            CVT_TF32(as[4], a1.x); CVT_TF32(as[5], a1.y); CVT_TF32(as[6], a1.z); CVT_TF32(as[7], a1.w);
            CVT_TF32(bs[0], b0.x); CVT_TF32(bs[1], b0.y); CVT_TF32(bs[2], b0.z); CVT_TF32(bs[3], b0.w);
            CVT_TF32(bs[4], b1.x); CVT_TF32(bs[5], b1.y); CVT_TF32(bs[6], b1.z); CVT_TF32(bs[7], b1.w);
            __syncthreads();
        }
    }
    __syncthreads();

    float* ep = epi + wid * 16 * LDS_;
#pragma unroll
    for (int fm = 0; fm < 4; fm++) {
#pragma unroll
        for (int fn = 0; fn < 2; fn++) {
            wmma::store_matrix_sync(ep, acc[fm][fn], LDS_, wmma::mem_row_major);
            __syncwarp();
            int r  = lane >> 1;
            int c8 = (lane & 1) * 8;
            int grow = bm + wm + fm * 16 + r;
            int gcol = bn + wn + fn * 16 + c8;
            size_t gidx = (size_t)grow * N + gcol;
            float o[8];
#pragma unroll
            for (int q = 0; q < 8; q++) {
                float cv = ep[r * LDS_ + c8 + q] + bias[gcol + q];
                if (EPI == 1) cv += res[gidx + q];
                if (EPI == 2) cv = cv / (1.f + __expf(-1.702f * cv));
                o[q] = cv;
            }
            *(float4*)&C[gidx]     = make_float4(o[0], o[1], o[2], o[3]);
            *(float4*)&C[gidx + 4] = make_float4(o[4], o[5], o[6], o[7]);
            __syncwarp();
        }
    }
}

// ---------------- Flash attention via mma.sync tf32 ----------------
// CTA: 128 threads (4 warps), 64 q rows (16 per warp). KV tiles of 64.
// Smem: Ks[64][68] tf32, Vs[64][72] tf32, Ps[4][16][68] tf32.
#define KS_STR 68
#define VS_STR 72
#define PS_STR 68
#define ATT_SMEM ((64 * KS_STR + 64 * VS_STR + 4 * 16 * PS_STR) * 4)

__global__ __launch_bounds__(128) void attn_mma(const float* __restrict__ qkv,
                                                float* __restrict__ o)
{
    extern __shared__ float asmem[];
    float* Ks = asmem;                                  // [64][KS_STR]
    float* Vs = asmem + 64 * KS_STR;                    // [64][VS_STR]
    float* Ps = asmem + 64 * KS_STR + 64 * VS_STR;      // [4][16][PS_STR]

    const int tid  = threadIdx.x;
    const int w    = tid >> 5;
    const int lane = tid & 31;
    const int g = lane >> 2, t = lane & 3;
    const int qb = blockIdx.x * 64 + w * 16;
    const int h = blockIdx.y, n = blockIdx.z;

    const float qscale = 0.125f * 1.44269504088896f;   // scale * log2(e)

    // preload Q A-fragments (8 k-chunks of dh)
    uint32_t aq[8][4];
    {
        size_t r0 = ((size_t)(qb + g) * NB + n) * E3 + h * DH;
        size_t r1 = ((size_t)(qb + g + 8) * NB + n) * E3 + h * DH;
#pragma unroll
        for (int ch = 0; ch < 8; ch++) {
            float v0 = qkv[r0 + ch * 8 + t]     * qscale;
            float v1 = qkv[r1 + ch * 8 + t]     * qscale;
            float v2 = qkv[r0 + ch * 8 + t + 4] * qscale;
            float v3 = qkv[r1 + ch * 8 + t + 4] * qscale;
            CVT_TF32(aq[ch][0], v0); CVT_TF32(aq[ch][1], v1);
            CVT_TF32(aq[ch][2], v2); CVT_TF32(aq[ch][3], v3);
        }
    }

    float oc[8][4];
#pragma unroll
    for (int i = 0; i < 8; i++)
#pragma unroll
        for (int j = 0; j < 4; j++) oc[i][j] = 0.f;
    float m0 = -1e30f, m1 = -1e30f, l0 = 0.f, l1 = 0.f;

    const int srow  = tid >> 1;           // 0..63
    const int shalf = (tid & 1) * 32;     // 0 or 32

    for (int kb = 0; kb < L_SEQ / 64; kb++) {
        // ---- stage K ----
        size_t kbase = ((size_t)(kb * 64 + srow) * NB + n) * E3 + EMB + h * DH + shalf;
        float4 kr[8];
#pragma unroll
        for (int i = 0; i < 8; i++) kr[i] = *(const float4*)&qkv[kbase + 4 * i];
        __syncthreads();   // prior tile fully consumed
        {
            uint32_t* ks = (uint32_t*)&Ks[srow * KS_STR + shalf];
#pragma unroll
            for (int i = 0; i < 8; i++) {
                uint4 cv;
                CVT_TF32(cv.x, kr[i].x); CVT_TF32(cv.y, kr[i].y);
                CVT_TF32(cv.z, kr[i].z); CVT_TF32(cv.w, kr[i].w);
                *(uint4*)&ks[4 * i] = cv;
            }
        }
        // ---- stage V ----
        size_t vbase = kbase + EMB;
#pragma unroll
        for (int i = 0; i < 8; i++) kr[i] = *(const float4*)&qkv[vbase + 4 * i];
        {
            uint32_t* vs = (uint32_t*)&Vs[srow * VS_STR + shalf];
#pragma unroll
            for (int i = 0; i < 8; i++) {
                uint4 cv;
                CVT_TF32(cv.x, kr[i].x); CVT_TF32(cv.y, kr[i].y);
                CVT_TF32(cv.z, kr[i].z); CVT_TF32(cv.w, kr[i].w);
                *(uint4*)&vs[4 * i] = cv;
            }
        }
        __syncthreads();

        // ---- S = Q * K^T  (in log2 units) ----
        float sc[8][4];
#pragma unroll
        for (int i = 0; i < 8; i++)
#pragma unroll
            for (int j = 0; j < 4; j++) sc[i][j] = 0.f;

        const uint32_t* ksb = (const uint32_t*)Ks;
#pragma unroll
        for (int nt = 0; nt < 8; nt++) {
#pragma unroll
            for (int ch = 0; ch < 8; ch++) {
                uint32_t b0 = ksb[(nt * 8 + g) * KS_STR + ch * 8 + t];
                uint32_t b1 = ksb[(nt * 8 + g) * KS_STR + ch * 8 + t + 4];
                mma8(sc[nt], aq[ch], b0, b1);
            }
        }

        // ---- online softmax (rows g and g+8) ----
        float tm0 = -1e30f, tm1 = -1e30f;
#pragma unroll
        for (int nt = 0; nt < 8; nt++) {
            tm0 = fmaxf(tm0, fmaxf(sc[nt][0], sc[nt][1]));
            tm1 = fmaxf(tm1, fmaxf(sc[nt][2], sc[nt][3]));
        }
        tm0 = fmaxf(tm0, __shfl_xor_sync(0xffffffffu, tm0, 1));
        tm0 = fmaxf(tm0, __shfl_xor_sync(0xffffffffu, tm0, 2));
        tm1 = fmaxf(tm1, __shfl_xor_sync(0xffffffffu, tm1, 1));
        tm1 = fmaxf(tm1, __shfl_xor_sync(0xffffffffu, tm1, 2));

        float nm0 = fmaxf(m0, tm0), nm1 = fmaxf(m1, tm1);
        float al0 = ex2f(m0 - nm0), al1 = ex2f(m1 - nm1);
        m0 = nm0; m1 = nm1;

        float s0 = 0.f, s1 = 0.f;
#pragma unroll
        for (int nt = 0; nt < 8; nt++) {
            sc[nt][0] = ex2f(sc[nt][0] - m0);
            sc[nt][1] = ex2f(sc[nt][1] - m0);
            sc[nt][2] = ex2f(sc[nt][2] - m1);
            sc[nt][3] = ex2f(sc[nt][3] - m1);
            s0 += sc[nt][0] + sc[nt][1];
            s1 += sc[nt][2] + sc[nt][3];
        }
        s0 += __shfl_xor_sync(0xffffffffu, s0, 1);
        s0 += __shfl_xor_sync(0xffffffffu, s0, 2);
        s1 += __shfl_xor_sync(0xffffffffu, s1, 1);
        s1 += __shfl_xor_sync(0xffffffffu, s1, 2);
        l0 = l0 * al0 + s0;
        l1 = l1 * al1 + s1;
#pragma unroll
        for (int nt = 0; nt < 8; nt++) {
            oc[nt][0] *= al0; oc[nt][1] *= al0;
            oc[nt][2] *= al1; oc[nt][3] *= al1;
        }

        // ---- stage P (per-warp scratch) ----
        uint32_t* pw = (uint32_t*)(Ps + w * 16 * PS_STR);
        __syncwarp();
#pragma unroll
        for (int nt = 0; nt < 8; nt++) {
            uint2 p0, p1;
            CVT_TF32(p0.x, sc[nt][0]); CVT_TF32(p0.y, sc[nt][1]);
            CVT_TF32(p1.x, sc[nt][2]); CVT_TF32(p1.y, sc[nt][3]);
            *(uint2*)&pw[g * PS_STR + nt * 8 + 2 * t]       = p0;
            *(uint2*)&pw[(g + 8) * PS_STR + nt * 8 + 2 * t] = p1;
        }
        __syncwarp();

        // ---- O += P * V ----
        const uint32_t* vsb = (const uint32_t*)Vs;
#pragma unroll
        for (int ch = 0; ch < 8; ch++) {
            uint32_t ap[4];
            ap[0] = pw[g * PS_STR + ch * 8 + t];
            ap[1] = pw[(g + 8) * PS_STR + ch * 8 + t];
            ap[2] = pw[g * PS_STR + ch * 8 + t + 4];
            ap[3] = pw[(g + 8) * PS_STR + ch * 8 + t + 4];
#pragma unroll
            for (int nt = 0; nt < 8; nt++) {
                uint32_t b0 = vsb[(ch * 8 + t) * VS_STR + nt * 8 + g];
                uint32_t b1 = vsb[(ch * 8 + t + 4) * VS_STR + nt * 8 + g];
                mma8(oc[nt], ap, b0, b1);
            }
        }
    }

    // ---- epilogue ----
    float i0 = 1.f / l0, i1 = 1.f / l1;
    size_t o0 = ((size_t)(qb + g) * NB + n) * EMB + h * DH;
    size_t o1 = ((size_t)(qb + g + 8) * NB + n) * EMB + h * DH;
#pragma unroll
    for (int nt = 0; nt < 8; nt++) {
        *(float2*)&o[o0 + nt * 8 + 2 * t] = make_float2(oc[nt][0] * i0, oc[nt][1] * i0);
        *(float2*)&o[o1 + nt * 8 + 2 * t] = make_float2(oc[nt][2] * i1, oc[nt][3] * i1);
    }
}

// ---------------- launch ----------------
extern "C" void kernel_launch(void* const* d_in, const int* in_sizes, int n_in,
                              void* d_out, int out_size)
{
    const float* x      = (const float*)d_in[0];
    const float* ln1_w  = (const float*)d_in[1];
    const float* ln1_b  = (const float*)d_in[2];
    const float* w_qkv  = (const float*)d_in[3];
    const float* b_qkv  = (const float*)d_in[4];
    const float* w_out  = (const float*)d_in[5];
    const float* b_out  = (const float*)d_in[6];
    const float* ln2_w  = (const float*)d_in[7];
    const float* ln2_b  = (const float*)d_in[8];
    const float* w_fc   = (const float*)d_in[9];
    const float* b_fc   = (const float*)d_in[10];
    const float* w_proj = (const float*)d_in[11];
    const float* b_proj = (const float*)d_in[12];
    float* out = (float*)d_out;

    float *h, *qkv, *attn, *x1, *f;
    cudaGetSymbolAddress((void**)&h,    g_h);
    cudaGetSymbolAddress((void**)&qkv,  g_qkv);
    cudaGetSymbolAddress((void**)&attn, g_attn);
    cudaGetSymbolAddress((void**)&x1,   g_x1);
    cudaGetSymbolAddress((void**)&f,    g_f);

    cudaFuncSetAttribute(gemm_wmma<0>, cudaFuncAttributeMaxDynamicSharedMemorySize, GT_SMEM);
    cudaFuncSetAttribute(gemm_wmma<1>, cudaFuncAttributeMaxDynamicSharedMemorySize, GT_SMEM);
    cudaFuncSetAttribute(gemm_wmma<2>, cudaFuncAttributeMaxDynamicSharedMemorySize, GT_SMEM);
    cudaFuncSetAttribute(attn_mma,     cudaFuncAttributeMaxDynamicSharedMemorySize, ATT_SMEM);

    ln_kernel<<<ROWS, 256>>>(x, ln1_w, ln1_b, h);
    gemm_wmma<0><<<dim3(E3 / 128, ROWS / 128), 256, GT_SMEM>>>(h, w_qkv, b_qkv, nullptr, qkv,
                                                               ROWS, E3, EMB);
    attn_mma<<<dim3(L_SEQ / 64, NHEAD, NB), 128, ATT_SMEM>>>(qkv, attn);
    gemm_wmma<1><<<dim3(EMB / 128, ROWS / 128), 256, GT_SMEM>>>(attn, w_out, b_out, x, x1,
                                                                ROWS, EMB, EMB);
    ln_kernel<<<ROWS, 256>>>(x1, ln2_w, ln2_b, h);
    gemm_wmma<2><<<dim3(E4 / 128, ROWS / 128), 256, GT_SMEM>>>(h, w_fc, b_fc, nullptr, f,
                                                               ROWS, E4, EMB);
    gemm_wmma<1><<<dim3(EMB / 128, ROWS / 128), 256, GT_SMEM>>>(f, w_proj, b_proj, x1, out,
                                                                ROWS, EMB, E4);
}